// round 9
// baseline (speedup 1.0000x reference)
#include <cuda_runtime.h>
#include <cstdint>
#include <cstddef>
#include <math.h>

#define SEQ    2048
#define BATCH  64
#define HID    512
#define INDIM  256
#define NCTA   128
#define NTHR   512

typedef unsigned long long u64;

// ---------------- device globals (allocation-free scratch) ----------------
__device__ __align__(8) unsigned g_flags[NCTA];  // monotonic, [half*64 + tile]
__device__ float g_h0_all[(size_t)SEQ * BATCH * HID];
__device__ float g_h1_all[(size_t)SEQ * BATCH * HID];
// xp0[t][r][b], r = gate*512 + hu  (L0 input projections, all steps): 1 GB
__device__ float g_xp0[(size_t)SEQ * 4 * HID * BATCH];

// ---------------- packed fp32x2 + memory-model helpers ----------------
__device__ __forceinline__ u64 ffma2(u64 a, u64 b, u64 c) {
    u64 d;
    asm("fma.rn.f32x2 %0, %1, %2, %3;" : "=l"(d) : "l"(a), "l"(b), "l"(c));
    return d;
}
__device__ __forceinline__ u64 fadd2(u64 a, u64 b) {
    u64 d;
    asm("add.rn.f32x2 %0, %1, %2;" : "=l"(d) : "l"(a), "l"(b));
    return d;
}
__device__ __forceinline__ u64 splat2(float x) {
    u64 d;
    asm("mov.b64 %0, {%1, %1};" : "=l"(d) : "f"(x));
    return d;
}
__device__ __forceinline__ u64 pack2(float lo, float hi) {
    u64 d;
    asm("mov.b64 %0, {%1, %2};" : "=l"(d) : "f"(lo), "f"(hi));
    return d;
}
__device__ __forceinline__ float f2lo(u64 v) { return __uint_as_float((unsigned)v); }
__device__ __forceinline__ float f2hi(u64 v) { return __uint_as_float((unsigned)(v >> 32)); }

__device__ __forceinline__ u64 shflx64(u64 v, int m) {
    unsigned lo = (unsigned)v, hi = (unsigned)(v >> 32);
    lo = __shfl_xor_sync(0xffffffffu, lo, m);
    hi = __shfl_xor_sync(0xffffffffu, hi, m);
    return ((u64)hi << 32) | (u64)lo;
}
__device__ __forceinline__ u64 shfli64(u64 v, int src) {
    unsigned lo = (unsigned)v, hi = (unsigned)(v >> 32);
    lo = __shfl_sync(0xffffffffu, lo, src);
    hi = __shfl_sync(0xffffffffu, hi, src);
    return ((u64)hi << 32) | (u64)lo;
}
__device__ __forceinline__ unsigned ld_rlx(const unsigned* p) {
    unsigned v;
    asm volatile("ld.relaxed.gpu.u32 %0, [%1];" : "=r"(v) : "l"(p));
    return v;
}
__device__ __forceinline__ void ld_rlx2(const unsigned* p, unsigned& a, unsigned& b) {
    asm volatile("ld.relaxed.gpu.v2.u32 {%0,%1}, [%2];"
                 : "=r"(a), "=r"(b) : "l"(p));
}
__device__ __forceinline__ void st_rlx(unsigned* p, unsigned v) {
    asm volatile("st.relaxed.gpu.u32 [%0], %1;" :: "l"(p), "r"(v) : "memory");
}
__device__ __forceinline__ void fence_acq() {
    asm volatile("fence.acq_rel.gpu;" ::: "memory");
}
__device__ __forceinline__ float sigf(float x) { return 1.0f / (1.0f + __expf(-x)); }
__device__ __forceinline__ float tanhfast(float x) {
    return 2.0f / (1.0f + __expf(-2.0f * x)) - 1.0f;
}

// =====================================================================
// Kernel 1: xp0[t][r][b] = sum_k W_ih0[r][k] * x[t][b][k]
// =====================================================================
__global__ void __launch_bounds__(256, 1)
xproj0_kernel(const float* __restrict__ x,      // [SEQ][BATCH][INDIM]
              const float* __restrict__ w_ih0)  // [4H][INDIM]
{
    constexpr int TS = 8;
    extern __shared__ float sm[];
    float* w_sm = sm;                 // [256 k][128 rows]
    float* x_sm = w_sm + 256 * 128;   // [256 k][64 b] quad-swizzled

    const int tid  = threadIdx.x;
    const int rowTile = blockIdx.x & 15;
    const int t0      = (blockIdx.x >> 4) * TS;

    for (int idx = tid; idx < 128 * INDIM; idx += 256) {
        int lr = idx >> 8;
        int k  = idx & 255;
        w_sm[k * 128 + lr] = w_ih0[(size_t)(rowTile * 128 + lr) * INDIM + k];
    }

    const int bg = tid & 7;           // batch group (8 batches)
    const int pg = tid >> 3;          // pair-group: rows 4pg..4pg+3
    const int c  = tid >> 4;          // staging batch-quad 0..15
    const int kl = tid & 15;

    for (int tt = 0; tt < TS; tt++) {
        const int t = t0 + tt;
        __syncthreads();              // protect x_sm reuse (covers W 1st iter)
        {   // stage x tile, quad-XOR swizzled
            const float* xs = x + ((size_t)t * BATCH + 4 * c) * INDIM;
#pragma unroll
            for (int i = 0; i < 16; i++) {
                int k = kl + 16 * i;
                float v0 = __ldg(xs + k);
                float v1 = __ldg(xs + INDIM + k);
                float v2 = __ldg(xs + 2 * INDIM + k);
                float v3 = __ldg(xs + 3 * INDIM + k);
                *(float4*)(x_sm + k * 64 + ((c ^ (k & 15)) << 2)) =
                    make_float4(v0, v1, v2, v3);
            }
        }
        __syncthreads();

        u64 acc[2][8];
#pragma unroll
        for (int e = 0; e < 2; e++)
#pragma unroll
            for (int b = 0; b < 8; b++) acc[e][b] = 0ull;

        const float* wp = w_sm + 4 * pg;
#pragma unroll 4
        for (int k = 0; k < INDIM; k++) {
            ulonglong2 wA = *(const ulonglong2*)(wp + (size_t)k * 128);
            float4 aA = *(const float4*)(x_sm + k * 64 + (((2 * bg)     ^ (k & 15)) << 2));
            float4 aB = *(const float4*)(x_sm + k * 64 + (((2 * bg + 1) ^ (k & 15)) << 2));
            u64 a2[8];
            a2[0] = splat2(aA.x); a2[1] = splat2(aA.y);
            a2[2] = splat2(aA.z); a2[3] = splat2(aA.w);
            a2[4] = splat2(aB.x); a2[5] = splat2(aB.y);
            a2[6] = splat2(aB.z); a2[7] = splat2(aB.w);
#pragma unroll
            for (int b = 0; b < 8; b++) {
                acc[0][b] = ffma2(wA.x, a2[b], acc[0][b]);
                acc[1][b] = ffma2(wA.y, a2[b], acc[1][b]);
            }
        }

#pragma unroll
        for (int e = 0; e < 2; e++) {
            int pa = 2 * pg + e;
            float lo[8], hi[8];
#pragma unroll
            for (int b = 0; b < 8; b++) { lo[b] = f2lo(acc[e][b]); hi[b] = f2hi(acc[e][b]); }
            size_t rb = ((size_t)t * 2048 + rowTile * 128 + 2 * pa) * 64 + 8 * bg;
            *(float4*)(g_xp0 + rb)      = make_float4(lo[0], lo[1], lo[2], lo[3]);
            *(float4*)(g_xp0 + rb + 4)  = make_float4(lo[4], lo[5], lo[6], lo[7]);
            *(float4*)(g_xp0 + rb + 64) = make_float4(hi[0], hi[1], hi[2], hi[3]);
            *(float4*)(g_xp0 + rb + 68) = make_float4(hi[4], hi[5], hi[6], hi[7]);
        }
    }
}

// =====================================================================
// Kernel 2: fused 2-layer persistent LSTM, wavefront-pipelined.
//  Iteration n: L1 step n-1, L0 step n. ONE barrier per iteration.
// =====================================================================
__global__ void __launch_bounds__(NTHR, 1)
lstm_fused(const float* __restrict__ h0i,     // [2][BATCH][HID]
           const float* __restrict__ c0i,     // [2][BATCH][HID]
           const float* __restrict__ w_hh0,
           const float* __restrict__ b_ih0, const float* __restrict__ b_hh0,
           const float* __restrict__ w_ih1,
           const float* __restrict__ w_hh1,
           const float* __restrict__ b_ih1, const float* __restrict__ b_hh1)
{
    extern __shared__ float smem[];
    float* wh0     = smem;                    // 16384
    float* wx1     = wh0 + HID * 32;          // 16384
    float* wh1     = wx1 + HID * 32;          // 16384
    float* buf0    = wh1 + HID * 32;          // 4096
    float* buf1    = buf0 + 128 * 32;         // 4096
    float* bias_sm = buf1 + 128 * 32;         // 64

    const int tid  = threadIdx.x;
    const int lane = tid & 31;
    const int wrp  = tid >> 5;
    const int rg   = wrp & 3;
    const int bg   = wrp >> 2;
    const int half = blockIdx.x & 1;
    const int hu_base = (blockIdx.x >> 1) * 8;
    const int bbase   = half * 32;
    const int fidx    = half * 64 + (blockIdx.x >> 1);

    auto loadW = [&](float* dst, const float* W) {
        for (int r = 0; r < 32; r++) {
            int gate = r >> 3, hl = r & 7;
            const float* wr = W + (size_t)(gate * HID + hu_base + hl) * HID;
            int qnat = 2 * (hl >> 1) + (gate >> 1);
            int sub  = ((gate & 1) << 1) | (hl & 1);
            for (int k = tid; k < HID; k += NTHR)
                dst[k * 32 + ((qnat ^ (k & 7)) << 2) + sub] = wr[k];
        }
    };
    loadW(wh0, w_hh0);
    loadW(wx1, w_ih1);
    loadW(wh1, w_hh1);
    if (tid < 64) {
        int layer = tid >> 5, r = tid & 31;
        int gate = r >> 3, hl = r & 7;
        int R = gate * HID + hu_base + hl;
        int pair = (hl >> 1) * 4 + gate;
        float bv = layer ? (b_ih1[R] + b_hh1[R]) : (b_ih0[R] + b_hh0[R]);
        bias_sm[layer * 32 + pair * 2 + (hl & 1)] = bv;
    }

    __shared__ unsigned s_base;
    if (tid == 0) s_base = ld_rlx(&g_flags[fidx]);
    __syncthreads();
    const unsigned base = s_base;

    const int q0off = ((2 * rg)     ^ (lane & 7)) << 2;
    const int q1off = ((2 * rg + 1) ^ (lane & 7)) << 2;
    const int a0off = ((2 * bg)     ^ (lane & 7)) << 2;
    const int a1off = ((2 * bg + 1) ^ (lane & 7)) << 2;

    const int bb  = bg * 8 + (lane & 7);
    const int hu0 = hu_base + rg * 2;
    const float* h0l0 = h0i;
    const float* h0l1 = h0i + BATCH * HID;
    float c0r0 = c0i[(size_t)(bbase + bb) * HID + hu0];
    float c0r1 = c0i[(size_t)(bbase + bb) * HID + hu0 + 1];
    float c1r0 = c0i[(size_t)(BATCH * HID) + (size_t)(bbase + bb) * HID + hu0];
    float c1r1 = c0i[(size_t)(BATCH * HID) + (size_t)(bbase + bb) * HID + hu0 + 1];

    u64 acc[4][8];
#pragma unroll
    for (int g = 0; g < 4; g++)
#pragma unroll
        for (int b = 0; b < 8; b++) acc[g][b] = 0ull;

    const int stC   = wrp & 7;
    const int stKg0 = wrp >> 3;
    const int stCo  = (stC ^ (lane & 7)) << 2;

    // stage 128-k chunk at global offset koff into buf (chunk-local rows)
    auto stage = [&](float* buf, const float* src, int koff) {
        const float* s0 = src + (size_t)(bbase + 4 * stC) * HID + koff;
#pragma unroll
        for (int i = 0; i < 2; i++) {
            int k = 32 * (stKg0 + 2 * i) + lane;   // chunk-local 0..127
            const float* s = s0 + k;
            float v0 = __ldg(s);
            float v1 = __ldg(s + HID);
            float v2 = __ldg(s + 2 * HID);
            float v3 = __ldg(s + 3 * HID);
            *(float4*)(buf + k * 32 + stCo) = make_float4(v0, v1, v2, v3);   // FIXED
        }
    };

    auto compute = [&](const float* wmat, const float* buf, int chunk) {
        const float* wp = wmat + (size_t)(chunk * 128 + lane) * 32;
        const float* ap = buf + lane * 32;
#pragma unroll
        for (int j = 0; j < 4; j++) {
            u64 w2[4];
            {
                ulonglong2 wA = *(const ulonglong2*)(wp + j * 1024 + q0off);
                ulonglong2 wB = *(const ulonglong2*)(wp + j * 1024 + q1off);
                w2[0] = wA.x; w2[1] = wA.y; w2[2] = wB.x; w2[3] = wB.y;
            }
            float4 aA = *(const float4*)(ap + j * 1024 + a0off);
            float4 aB = *(const float4*)(ap + j * 1024 + a1off);
            u64 a2[8];
            a2[0] = splat2(aA.x); a2[1] = splat2(aA.y);
            a2[2] = splat2(aA.z); a2[3] = splat2(aA.w);
            a2[4] = splat2(aB.x); a2[5] = splat2(aB.y);
            a2[6] = splat2(aB.z); a2[7] = splat2(aB.w);
#pragma unroll
            for (int b = 0; b < 8; b++)
#pragma unroll
                for (int g = 0; g < 4; g++)
                    acc[g][b] = ffma2(w2[g], a2[b], acc[g][b]);
        }
    };

    auto run4 = [&](const float* wmat, const float* src) {
        stage(buf0, src, 0);
        __syncthreads();
        stage(buf1, src, 128);
        compute(wmat, buf0, 0);
        __syncthreads();
        stage(buf0, src, 256);
        compute(wmat, buf1, 1);
        __syncthreads();
        stage(buf1, src, 384);
        compute(wmat, buf0, 2);
        __syncthreads();
        compute(wmat, buf1, 3);
    };

#define ACCF(i) acc[(i) >> 3][(i) & 7]
    auto reduce = [&]() -> u64 {
#pragma unroll
        for (int i = 0; i < 16; i++) {
            u64 lo = ACCF(i), hi = ACCF(i + 16);
            u64 mine = (lane & 16) ? hi : lo;
            u64 give = (lane & 16) ? lo : hi;
            ACCF(i) = fadd2(mine, shflx64(give, 16));
        }
#pragma unroll
        for (int i = 0; i < 8; i++) {
            u64 lo = ACCF(i), hi = ACCF(i + 8);
            u64 mine = (lane & 8) ? hi : lo;
            u64 give = (lane & 8) ? lo : hi;
            ACCF(i) = fadd2(mine, shflx64(give, 8));
        }
#pragma unroll
        for (int i = 0; i < 4; i++) {
            u64 lo = ACCF(i), hi = ACCF(i + 4);
            u64 mine = (lane & 4) ? hi : lo;
            u64 give = (lane & 4) ? lo : hi;
            ACCF(i) = fadd2(mine, shflx64(give, 4));
        }
#pragma unroll
        for (int i = 0; i < 2; i++) {
            u64 lo = ACCF(i), hi = ACCF(i + 2);
            u64 mine = (lane & 2) ? hi : lo;
            u64 give = (lane & 2) ? lo : hi;
            ACCF(i) = fadd2(mine, shflx64(give, 2));
        }
        {
            u64 lo = ACCF(0), hi = ACCF(1);
            u64 mine = (lane & 1) ? hi : lo;
            u64 give = (lane & 1) ? lo : hi;
            ACCF(0) = fadd2(mine, shflx64(give, 1));
        }
        return ACCF(0);
    };
    auto zeroacc = [&]() {
#pragma unroll
        for (int g = 0; g < 4; g++)
#pragma unroll
            for (int b = 0; b < 8; b++) acc[g][b] = 0ull;
    };

    for (int n = 0; n <= SEQ; ++n) {
        if (n > 0 && wrp == 0) {
            const unsigned target = base + (unsigned)n;
            const unsigned* fp = g_flags + half * 64 + lane * 2;
            for (;;) {
                unsigned a, b;
                ld_rlx2(fp, a, b);
                if ((int)(a - target) >= 0 && (int)(b - target) >= 0) break;
            }
            fence_acq();
        }
        __syncthreads();

        float xpv[8];
        if (n < SEQ) {
            const float* xp = g_xp0 + ((size_t)n * 2048 + hu0) * 64 + bbase + bb;
#pragma unroll
            for (int g = 0; g < 4; g++) {
                xpv[2 * g]     = __ldg(xp + (size_t)(g * 512) * 64);
                xpv[2 * g + 1] = __ldg(xp + (size_t)(g * 512 + 1) * 64);
            }
        }

        // ---- L1 step n-1 ----
        if (n >= 1) {
            const float* h0p = g_h0_all + (size_t)(n - 1) * BATCH * HID;
            const float* h1p = (n == 1) ? h0l1
                               : g_h1_all + (size_t)(n - 2) * BATCH * HID;
            run4(wx1, h0p);
            __syncthreads();
            run4(wh1, h1p);
            u64 fin = reduce();
            const u64* b1 = (const u64*)(bias_sm + 32);
            u64 gv[4];
#pragma unroll
            for (int g = 0; g < 4; g++)
                gv[g] = fadd2(shfli64(fin, g * 8 + (lane & 7)), b1[rg * 4 + g]);
            float ig0 = sigf(f2lo(gv[0])), ig1 = sigf(f2hi(gv[0]));
            float fg0 = sigf(f2lo(gv[1])), fg1 = sigf(f2hi(gv[1]));
            float gg0 = tanhfast(f2lo(gv[2])), gg1 = tanhfast(f2hi(gv[2]));
            float og0 = sigf(f2lo(gv[3])), og1 = sigf(f2hi(gv[3]));
            c1r0 = fg0 * c1r0 + ig0 * gg0;
            c1r1 = fg1 * c1r1 + ig1 * gg1;
            if (lane < 8)
                *(float2*)&g_h1_all[((size_t)(n - 1) * BATCH + bbase + bb) * HID + hu0] =
                    make_float2(og0 * tanhfast(c1r0), og1 * tanhfast(c1r1));
            zeroacc();
        }

        // ---- L0 step n ----
        if (n < SEQ) {
            const float* hp = (n == 0) ? h0l0
                              : g_h0_all + (size_t)(n - 1) * BATCH * HID;
            if (n >= 1) __syncthreads();
            run4(wh0, hp);
            u64 fin = reduce();
            const u64* b0 = (const u64*)bias_sm;
            u64 gv[4];
#pragma unroll
            for (int g = 0; g < 4; g++)
                gv[g] = fadd2(fadd2(shfli64(fin, g * 8 + (lane & 7)), b0[rg * 4 + g]),
                              pack2(xpv[2 * g], xpv[2 * g + 1]));
            float ig0 = sigf(f2lo(gv[0])), ig1 = sigf(f2hi(gv[0]));
            float fg0 = sigf(f2lo(gv[1])), fg1 = sigf(f2hi(gv[1]));
            float gg0 = tanhfast(f2lo(gv[2])), gg1 = tanhfast(f2hi(gv[2]));
            float og0 = sigf(f2lo(gv[3])), og1 = sigf(f2hi(gv[3]));
            c0r0 = fg0 * c0r0 + ig0 * gg0;
            c0r1 = fg1 * c0r1 + ig1 * gg1;
            if (lane < 8)
                *(float2*)&g_h0_all[((size_t)n * BATCH + bbase + bb) * HID + hu0] =
                    make_float2(og0 * tanhfast(c0r0), og1 * tanhfast(c0r1));
            zeroacc();
        }

        if (n < SEQ) {
            __threadfence();
            __syncthreads();
            if (tid == 0) st_rlx(&g_flags[fidx], base + (unsigned)(n + 1));
        }
    }
#undef ACCF
}

// ---------------- output head: sigmoid(h1 . w_out + b_out) ----------------
__global__ void __launch_bounds__(256)
head_kernel(const float* __restrict__ w_out, const float* __restrict__ b_out,
            float* __restrict__ out)
{
    __shared__ float wsm[HID];
    int t = blockIdx.x;
    for (int i = threadIdx.x; i < HID; i += 256) wsm[i] = w_out[i];
    __syncthreads();
    int wrp = threadIdx.x >> 5, lane = threadIdx.x & 31;
    float bo = b_out[0];
#pragma unroll
    for (int rb = 0; rb < 8; ++rb) {
        int b = wrp * 8 + rb;
        const float* h = g_h1_all + ((size_t)t * BATCH + b) * HID;
        float s = 0.f;
#pragma unroll
        for (int j = 0; j < 16; ++j) s += h[lane + 32 * j] * wsm[lane + 32 * j];
#pragma unroll
        for (int m = 16; m > 0; m >>= 1) s += __shfl_xor_sync(0xffffffffu, s, m);
        if (lane == 0) out[(size_t)t * BATCH + b] = 1.f / (1.f + expf(-(s + bo)));
    }
}

extern "C" void kernel_launch(void* const* d_in, const int* in_sizes, int n_in,
                              void* d_out, int out_size)
{
    (void)in_sizes; (void)n_in; (void)out_size;
    const float* input = (const float*)d_in[0];
    const float* h0    = (const float*)d_in[1];
    const float* c0    = (const float*)d_in[2];
    const float* w_ih0 = (const float*)d_in[3];
    const float* w_hh0 = (const float*)d_in[4];
    const float* b_ih0 = (const float*)d_in[5];
    const float* b_hh0 = (const float*)d_in[6];
    const float* w_ih1 = (const float*)d_in[7];
    const float* w_hh1 = (const float*)d_in[8];
    const float* b_ih1 = (const float*)d_in[9];
    const float* b_hh1 = (const float*)d_in[10];
    const float* w_out = (const float*)d_in[11];
    const float* b_out = (const float*)d_in[12];
    float* out = (float*)d_out;

    const int smemX = (256 * 128 + 256 * 64) * (int)sizeof(float);              // 196,608
    const int smemF = (3 * HID * 32 + 2 * 128 * 32 + 64) * (int)sizeof(float);  // 229,632
    cudaFuncSetAttribute(xproj0_kernel, cudaFuncAttributeMaxDynamicSharedMemorySize, smemX);
    cudaFuncSetAttribute(lstm_fused,    cudaFuncAttributeMaxDynamicSharedMemorySize, smemF);

    xproj0_kernel<<<16 * 256, 256, smemX>>>(input, w_ih0);
    lstm_fused<<<NCTA, NTHR, smemF>>>(h0, c0, w_hh0, b_ih0, b_hh0,
                                      w_ih1, w_hh1, b_ih1, b_hh1);
    head_kernel<<<SEQ, 256>>>(w_out, b_out, out);
}

// round 10
// speedup vs baseline: 1.0989x; 1.0989x over previous
#include <cuda_runtime.h>
#include <cstdint>
#include <cstddef>
#include <math.h>

#define SEQ    2048
#define BATCH  64
#define HID    512
#define NCTA   128
#define NTHR   512

typedef unsigned long long u64;

// ---------------- device globals (allocation-free scratch) ----------------
__device__ __align__(8) unsigned g_flags[NCTA];  // monotonic, [half*64 + tile]
__device__ float g_h0_all[(size_t)SEQ * BATCH * HID];
__device__ float g_h1_all[(size_t)SEQ * BATCH * HID];

// ---------------- packed fp32x2 + memory-model helpers ----------------
__device__ __forceinline__ u64 ffma2(u64 a, u64 b, u64 c) {
    u64 d;
    asm("fma.rn.f32x2 %0, %1, %2, %3;" : "=l"(d) : "l"(a), "l"(b), "l"(c));
    return d;
}
__device__ __forceinline__ u64 fadd2(u64 a, u64 b) {
    u64 d;
    asm("add.rn.f32x2 %0, %1, %2;" : "=l"(d) : "l"(a), "l"(b));
    return d;
}
__device__ __forceinline__ u64 splat2(float x) {
    u64 d;
    asm("mov.b64 %0, {%1, %1};" : "=l"(d) : "f"(x));
    return d;
}
__device__ __forceinline__ float f2lo(u64 v) { return __uint_as_float((unsigned)v); }
__device__ __forceinline__ float f2hi(u64 v) { return __uint_as_float((unsigned)(v >> 32)); }

__device__ __forceinline__ u64 shflx64(u64 v, int m) {
    unsigned lo = (unsigned)v, hi = (unsigned)(v >> 32);
    lo = __shfl_xor_sync(0xffffffffu, lo, m);
    hi = __shfl_xor_sync(0xffffffffu, hi, m);
    return ((u64)hi << 32) | (u64)lo;
}
__device__ __forceinline__ u64 shfli64(u64 v, int src) {
    unsigned lo = (unsigned)v, hi = (unsigned)(v >> 32);
    lo = __shfl_sync(0xffffffffu, lo, src);
    hi = __shfl_sync(0xffffffffu, hi, src);
    return ((u64)hi << 32) | (u64)lo;
}
__device__ __forceinline__ unsigned ld_rlx(const unsigned* p) {
    unsigned v;
    asm volatile("ld.relaxed.gpu.u32 %0, [%1];" : "=r"(v) : "l"(p));
    return v;
}
__device__ __forceinline__ void ld_rlx2(const unsigned* p, unsigned& a, unsigned& b) {
    asm volatile("ld.relaxed.gpu.v2.u32 {%0,%1}, [%2];"
                 : "=r"(a), "=r"(b) : "l"(p));
}
__device__ __forceinline__ void st_rlx(unsigned* p, unsigned v) {
    asm volatile("st.relaxed.gpu.u32 [%0], %1;" :: "l"(p), "r"(v) : "memory");
}
__device__ __forceinline__ void fence_acq() {
    asm volatile("fence.acq_rel.gpu;" ::: "memory");
}
__device__ __forceinline__ float sigf(float x) { return 1.0f / (1.0f + __expf(-x)); }
__device__ __forceinline__ float tanhfast(float x) {
    return 2.0f / (1.0f + __expf(-2.0f * x)) - 1.0f;
}

// =====================================================================
// Persistent fused LSTM layer, v6 (R7 + overhead surgery).
//  Per step: S1 (poll join) / stage both h chunks / S2 / compute both /
//  stage x(t+1) chunk0 (pre-reduce; S3 covers its STS) / reduce+cell /
//  fence / S3 / flag / compute x chunk0 [/ stage+S4+compute x chunk1].
//  Syncs: 3 (L0), 4 (L1)  — was 5 / 6 in R7.
// =====================================================================
template<int DIN>
__global__ void __launch_bounds__(NTHR, 1)
lstm_layer(const float* __restrict__ x,       // [SEQ][BATCH][DIN]
           const float* __restrict__ h0l,     // [BATCH][HID]
           const float* __restrict__ c0l,     // [BATCH][HID]
           const float* __restrict__ w_ih,    // [4H][DIN]
           const float* __restrict__ w_hh,    // [4H][HID]
           const float* __restrict__ b_ih,    // [4H]
           const float* __restrict__ b_hh,    // [4H]
           float* __restrict__ h_all)         // [SEQ][BATCH][HID]
{
    constexpr int K   = HID + DIN;            // 768 or 1024
    constexpr int NXC = DIN / 256;            // 1 or 2 x-chunks

    extern __shared__ float smem[];
    float* w_sm    = smem;                    // K*32  (quad-swizzled, rg-major)
    float* buf0    = w_sm + K * 32;           // 256*32
    float* buf1    = buf0 + 256 * 32;         // 256*32
    float* buf2    = buf1 + 256 * 32;         // 256*32
    float* bias_sm = buf2 + 256 * 32;         // 32 (pair-major)

    const int tid  = threadIdx.x;
    const int lane = tid & 31;
    const int wrp  = tid >> 5;                // 0..15
    const int rg   = wrp & 3;                 // hu-pair group
    const int bg   = wrp >> 2;                // batch group (8 batches)
    const int half = blockIdx.x & 1;          // batch half
    const int hu_base = (blockIdx.x >> 1) * 8;
    const int bbase   = half * 32;
    const int fidx    = half * 64 + (blockIdx.x >> 1);

    // ---- one-time: weights into SMEM, rg-major pairs, quad-XOR swizzle ----
    for (int r = 0; r < 32; r++) {
        int gate = r >> 3, hl = r & 7;
        int rgf = hl >> 1;
        int R = gate * HID + hu_base + hl;
        int qnat = 2 * rgf + (gate >> 1);
        int sub  = ((gate & 1) << 1) | (hl & 1);
        const float* wr_h = w_hh + (size_t)R * HID;
        const float* wr_x = w_ih + (size_t)R * DIN;
        for (int k = tid; k < K; k += NTHR) {
            float v = (k < HID) ? wr_h[k] : wr_x[k - HID];
            w_sm[k * 32 + ((qnat ^ (k & 7)) << 2) + sub] = v;
        }
    }
    if (tid < 32) {
        int gate = tid >> 3, hl = tid & 7;
        int R = gate * HID + hu_base + hl;
        int pair = (hl >> 1) * 4 + gate;
        bias_sm[pair * 2 + (hl & 1)] = b_ih[R] + b_hh[R];
    }

    __shared__ unsigned s_base;
    if (tid == 0) s_base = ld_rlx(&g_flags[fidx]);
    __syncthreads();                          // covers weights/bias too
    const unsigned base = s_base;

    u64 bias2[4];
#pragma unroll
    for (int g = 0; g < 4; g++) bias2[g] = ((const u64*)bias_sm)[rg * 4 + g];

    const int q0off = ((2 * rg)     ^ (lane & 7)) << 2;
    const int q1off = ((2 * rg + 1) ^ (lane & 7)) << 2;
    const int a0off = ((2 * bg)     ^ (lane & 7)) << 2;
    const int a1off = ((2 * bg + 1) ^ (lane & 7)) << 2;

    const int bb  = bg * 8 + (lane & 7);
    const int hu0 = hu_base + rg * 2;
    float c0r = c0l[(size_t)(bbase + bb) * HID + hu0];
    float c1r = c0l[(size_t)(bbase + bb) * HID + hu0 + 1];

    u64 acc[4][8];
#pragma unroll
    for (int g = 0; g < 4; g++)
#pragma unroll
        for (int b = 0; b < 8; b++) acc[g][b] = 0ull;

    // staging identity: thread stages batch-quad stC at k = 32*(stKg0+2i)+lane
    const int stC   = wrp & 7;
    const int stKg0 = wrp >> 3;
    const int stCo  = (stC ^ (lane & 7)) << 2;

    // stage one 256-k chunk (chunk-local rows) from src at column offset koff
    auto stage = [&](float* buf, const float* src, int stride, int koff) {
        const float* s0 = src + (size_t)(bbase + 4 * stC) * stride + koff;
#pragma unroll
        for (int i = 0; i < 4; i++) {
            int k = 32 * (stKg0 + 2 * i) + lane;   // chunk-local 0..255
            const float* s = s0 + k;
            float v0 = __ldg(s);
            float v1 = __ldg(s + stride);
            float v2 = __ldg(s + 2 * stride);
            float v3 = __ldg(s + 3 * stride);
            *(float4*)(buf + k * 32 + stCo) = make_float4(v0, v1, v2, v3);
        }
    };

    auto compute = [&](const float* buf, int kbase) {
        const float* wp = w_sm + (size_t)(kbase + lane) * 32;
        const float* ap = buf + lane * 32;
#pragma unroll
        for (int j = 0; j < 8; j++) {
            u64 w2[4];
            {
                ulonglong2 wA = *(const ulonglong2*)(wp + j * 1024 + q0off);
                ulonglong2 wB = *(const ulonglong2*)(wp + j * 1024 + q1off);
                w2[0] = wA.x; w2[1] = wA.y; w2[2] = wB.x; w2[3] = wB.y;
            }
            float4 aA = *(const float4*)(ap + j * 1024 + a0off);
            float4 aB = *(const float4*)(ap + j * 1024 + a1off);
            u64 a2[8];
            a2[0] = splat2(aA.x); a2[1] = splat2(aA.y);
            a2[2] = splat2(aA.z); a2[3] = splat2(aA.w);
            a2[4] = splat2(aB.x); a2[5] = splat2(aB.y);
            a2[6] = splat2(aB.z); a2[7] = splat2(aB.w);
#pragma unroll
            for (int b = 0; b < 8; b++)
#pragma unroll
                for (int g = 0; g < 4; g++)
                    acc[g][b] = ffma2(w2[g], a2[b], acc[g][b]);
        }
    };

#define ACCF(i) acc[(i) >> 3][(i) & 7]

    // ---- prologue: x-projection of step 0 into acc ----
    {
        stage(buf2, x, DIN, 0);
        if constexpr (NXC == 2) stage(buf0, x, DIN, 256);
        __syncthreads();
        compute(buf2, HID);
        if constexpr (NXC == 2) compute(buf0, HID + 256);
    }

    for (int t = 0; t < SEQ; ++t) {
        const float* __restrict__ hprev =
            t ? (h_all + (size_t)(t - 1) * BATCH * HID) : h0l;

        // ---- tight spin poll on own half's 64 flags (warp 0 only) ----
        if (t > 0 && wrp == 0) {
            const unsigned target = base + (unsigned)t;
            const unsigned* fp = g_flags + half * 64 + lane * 2;
            for (;;) {
                unsigned a, b;
                ld_rlx2(fp, a, b);
                if ((int)(a - target) >= 0 && (int)(b - target) >= 0) break;
            }
            fence_acq();
        }
        __syncthreads();                      // S1: join poll / prev tail compute

        // ---- h-part: stage both chunks under one sync, compute both ----
        stage(buf0, hprev, HID, 0);
        stage(buf1, hprev, HID, 256);
        __syncthreads();                      // S2
        compute(buf0, 0);
        compute(buf1, 256);

        // pre-stage x chunk 0 of step t+1 (no barrier dependency; buf2 free)
        const bool pre = (t + 1 < SEQ);
        const float* xn = x + (size_t)(t + 1) * BATCH * DIN;
        if (pre) stage(buf2, xn, DIN, 0);

        // ---- selection-compaction reduction over 32 k-lanes ----
#pragma unroll
        for (int i = 0; i < 16; i++) {
            u64 lo = ACCF(i), hi = ACCF(i + 16);
            u64 mine = (lane & 16) ? hi : lo;
            u64 give = (lane & 16) ? lo : hi;
            ACCF(i) = fadd2(mine, shflx64(give, 16));
        }
#pragma unroll
        for (int i = 0; i < 8; i++) {
            u64 lo = ACCF(i), hi = ACCF(i + 8);
            u64 mine = (lane & 8) ? hi : lo;
            u64 give = (lane & 8) ? lo : hi;
            ACCF(i) = fadd2(mine, shflx64(give, 8));
        }
#pragma unroll
        for (int i = 0; i < 4; i++) {
            u64 lo = ACCF(i), hi = ACCF(i + 4);
            u64 mine = (lane & 4) ? hi : lo;
            u64 give = (lane & 4) ? lo : hi;
            ACCF(i) = fadd2(mine, shflx64(give, 4));
        }
#pragma unroll
        for (int i = 0; i < 2; i++) {
            u64 lo = ACCF(i), hi = ACCF(i + 2);
            u64 mine = (lane & 2) ? hi : lo;
            u64 give = (lane & 2) ? lo : hi;
            ACCF(i) = fadd2(mine, shflx64(give, 2));
        }
        {
            u64 lo = ACCF(0), hi = ACCF(1);
            u64 mine = (lane & 1) ? hi : lo;
            u64 give = (lane & 1) ? lo : hi;
            ACCF(0) = fadd2(mine, shflx64(give, 1));
        }
        u64 fin = ACCF(0);

        u64 gv[4];
#pragma unroll
        for (int g = 0; g < 4; g++)
            gv[g] = fadd2(shfli64(fin, g * 8 + (lane & 7)), bias2[g]);

        float ig0 = sigf(f2lo(gv[0])), ig1 = sigf(f2hi(gv[0]));
        float fg0 = sigf(f2lo(gv[1])), fg1 = sigf(f2hi(gv[1]));
        float gg0 = tanhfast(f2lo(gv[2])), gg1 = tanhfast(f2hi(gv[2]));
        float og0 = sigf(f2lo(gv[3])), og1 = sigf(f2hi(gv[3]));
        c0r = fg0 * c0r + ig0 * gg0;
        c1r = fg1 * c1r + ig1 * gg1;
        float h0v = og0 * tanhfast(c0r);
        float h1v = og1 * tanhfast(c1r);

        if (lane < 8)
            *(float2*)&h_all[((size_t)t * BATCH + bbase + bb) * HID + hu0] =
                make_float2(h0v, h1v);

        // zero acc for next step's x accumulation
#pragma unroll
        for (int g = 0; g < 4; g++)
#pragma unroll
            for (int b = 0; b < 8; b++) acc[g][b] = 0ull;

        if (pre) {
            __threadfence();                  // h STG visible gpu-wide
            __syncthreads();                  // S3: fences joined; buf2 STS done
            if (tid == 0) st_rlx(&g_flags[fidx], base + (unsigned)(t + 1));
            // x-projection of step t+1: covers barrier propagation
            compute(buf2, HID);
            if constexpr (NXC == 2) {
                stage(buf0, xn, DIN, 256);
                __syncthreads();              // S4 (L1 only)
                compute(buf0, HID + 256);
            }
        }
    }
#undef ACCF
}

// ---------------- output head: sigmoid(h1 . w_out + b_out) ----------------
__global__ void __launch_bounds__(256)
head_kernel(const float* __restrict__ h_all, const float* __restrict__ w_out,
            const float* __restrict__ b_out, float* __restrict__ out)
{
    __shared__ float wsm[HID];
    int t = blockIdx.x;
    for (int i = threadIdx.x; i < HID; i += 256) wsm[i] = w_out[i];
    __syncthreads();
    int wrp = threadIdx.x >> 5, lane = threadIdx.x & 31;
    float bo = b_out[0];
#pragma unroll
    for (int rb = 0; rb < 8; ++rb) {
        int b = wrp * 8 + rb;
        const float* h = h_all + ((size_t)t * BATCH + b) * HID;
        float s = 0.f;
#pragma unroll
        for (int j = 0; j < 16; ++j) s += h[lane + 32 * j] * wsm[lane + 32 * j];
#pragma unroll
        for (int m = 16; m > 0; m >>= 1) s += __shfl_xor_sync(0xffffffffu, s, m);
        if (lane == 0) out[(size_t)t * BATCH + b] = 1.f / (1.f + expf(-(s + bo)));
    }
}

extern "C" void kernel_launch(void* const* d_in, const int* in_sizes, int n_in,
                              void* d_out, int out_size)
{
    (void)in_sizes; (void)n_in; (void)out_size;
    const float* input = (const float*)d_in[0];
    const float* h0    = (const float*)d_in[1];
    const float* c0    = (const float*)d_in[2];
    const float* w_ih0 = (const float*)d_in[3];
    const float* w_hh0 = (const float*)d_in[4];
    const float* b_ih0 = (const float*)d_in[5];
    const float* b_hh0 = (const float*)d_in[6];
    const float* w_ih1 = (const float*)d_in[7];
    const float* w_hh1 = (const float*)d_in[8];
    const float* b_ih1 = (const float*)d_in[9];
    const float* b_hh1 = (const float*)d_in[10];
    const float* w_out = (const float*)d_in[11];
    const float* b_out = (const float*)d_in[12];
    float* out = (float*)d_out;

    float* h0p = nullptr;
    float* h1p = nullptr;
    cudaGetSymbolAddress((void**)&h0p, g_h0_all);
    cudaGetSymbolAddress((void**)&h1p, g_h1_all);

    const int smem0 = (768  * 32 + 3 * 256 * 32 + 32) * (int)sizeof(float); // 196,736
    const int smem1 = (1024 * 32 + 3 * 256 * 32 + 32) * (int)sizeof(float); // 229,504
    cudaFuncSetAttribute(lstm_layer<256>, cudaFuncAttributeMaxDynamicSharedMemorySize, smem0);
    cudaFuncSetAttribute(lstm_layer<512>, cudaFuncAttributeMaxDynamicSharedMemorySize, smem1);

    lstm_layer<256><<<NCTA, NTHR, smem0>>>(input, h0, c0,
                                           w_ih0, w_hh0, b_ih0, b_hh0, h0p);
    lstm_layer<512><<<NCTA, NTHR, smem1>>>(h0p, h0 + BATCH * HID, c0 + BATCH * HID,
                                           w_ih1, w_hh1, b_ih1, b_hh1, h1p);
    head_kernel<<<SEQ, 256>>>(h1p, w_out, b_out, out);
}